// round 1
// baseline (speedup 1.0000x reference)
#include <cuda_runtime.h>
#include <math.h>

// Problem dims
#define B_  64
#define T_  512
#define F_  20
#define D_  1024
#define O_  1095
#define L_  3
#define M_  (B_ * T_)        // 32768 rows
#define N3_ (3 * D_)         // 3072
#define OPAD 1152            // O_ padded up to multiple of 128
#define Y_SIZE ((size_t)M_ * O_)

// Scratch (static device globals; no runtime allocation allowed)
__device__ float g_h[(size_t)M_ * D_];       // time-major hidden (t*B + b, d)
__device__ float g_hord[(size_t)M_ * D_];    // batch-major hidden (b*T + t, d)
__device__ float g_U[(size_t)M_ * N3_];      // SRU gate pre-activations
__device__ float g_W3p[(size_t)D_ * OPAD];   // zero-padded W3

// ---------------------------------------------------------------------------
// Input projection: h[t*B+b, d] = x[b,t,:] @ W1 + b1   (F=20 tiny K)
// ---------------------------------------------------------------------------
#define PROJ_ROWS 16
__global__ __launch_bounds__(256) void proj_kernel(
    const float* __restrict__ x, const float* __restrict__ W1,
    const float* __restrict__ b1)
{
    int r0 = blockIdx.x * PROJ_ROWS;
    __shared__ float xs[PROJ_ROWS][F_];
    for (int i = threadIdx.x; i < PROJ_ROWS * F_; i += blockDim.x) {
        int rr = i / F_, f = i % F_;
        int r = r0 + rr;
        int b = r % B_, t = r / B_;
        xs[rr][f] = x[((size_t)b * T_ + t) * F_ + f];
    }
    __syncthreads();
    for (int d = threadIdx.x; d < D_; d += blockDim.x) {
        float w[F_];
#pragma unroll
        for (int f = 0; f < F_; f++) w[f] = W1[f * D_ + d];
        float bb = b1[d];
#pragma unroll
        for (int rr = 0; rr < PROJ_ROWS; rr++) {
            float acc = bb;
#pragma unroll
            for (int f = 0; f < F_; f++) acc += xs[rr][f] * w[f];
            g_h[(size_t)(r0 + rr) * D_ + d] = acc;
        }
    }
}

// ---------------------------------------------------------------------------
// Zero-pad W3 (D x O) -> g_W3p (D x OPAD) so GEMM loads stay float4-aligned
// ---------------------------------------------------------------------------
__global__ void pad_w3_kernel(const float* __restrict__ W3)
{
    int idx = blockIdx.x * blockDim.x + threadIdx.x;
    if (idx < D_ * OPAD) {
        int k = idx / OPAD, n = idx % OPAD;
        g_W3p[idx] = (n < O_) ? W3[(size_t)k * O_ + n] : 0.0f;
    }
}

// ---------------------------------------------------------------------------
// Tiled fp32 SGEMM: C[M x storeN] = A[M x K] * B[K x N](ldb) (+bias)
// BM=BN=128, BK=16, 256 threads, 8x8 per-thread microtile.
// All loads are in-bounds by construction (M,K,N multiples of tile dims).
// ---------------------------------------------------------------------------
#define BM 128
#define BN 128
#define BKK 16
#define TM 8
#define TN 8
__global__ __launch_bounds__(256) void sgemm_kernel(
    const float* __restrict__ A, const float* __restrict__ Bm,
    float* __restrict__ C, int N, int K, int ldb, int ldc,
    const float* __restrict__ bias, int storeN)
{
    __shared__ float As[BKK][BM];
    __shared__ float Bs[BKK][BN];

    const int bm = blockIdx.y * BM;
    const int bn = blockIdx.x * BN;
    const int tid = threadIdx.x;
    const int tx = tid & 15;   // 16 cols of threads
    const int ty = tid >> 4;   // 16 rows of threads

    float acc[TM][TN];
#pragma unroll
    for (int i = 0; i < TM; i++)
#pragma unroll
        for (int j = 0; j < TN; j++) acc[i][j] = 0.0f;

    for (int k0 = 0; k0 < K; k0 += BKK) {
        // Load A tile (128x16) transposed into As[k][m]
#pragma unroll
        for (int jj = 0; jj < 2; jj++) {
            int l = tid + 256 * jj;
            int row = l >> 2, c4 = l & 3;
            float4 v = *(const float4*)&A[(size_t)(bm + row) * K + k0 + c4 * 4];
            As[c4 * 4 + 0][row] = v.x;
            As[c4 * 4 + 1][row] = v.y;
            As[c4 * 4 + 2][row] = v.z;
            As[c4 * 4 + 3][row] = v.w;
        }
        // Load B tile (16x128)
#pragma unroll
        for (int jj = 0; jj < 2; jj++) {
            int l = tid + 256 * jj;
            int row = l >> 5, c4 = l & 31;
            *(float4*)&Bs[row][c4 * 4] =
                *(const float4*)&Bm[(size_t)(k0 + row) * ldb + bn + c4 * 4];
        }
        __syncthreads();

#pragma unroll
        for (int k = 0; k < BKK; k++) {
            float a[TM], bv[TN];
            *(float4*)&a[0]  = *(const float4*)&As[k][ty * TM + 0];
            *(float4*)&a[4]  = *(const float4*)&As[k][ty * TM + 4];
            *(float4*)&bv[0] = *(const float4*)&Bs[k][tx * TN + 0];
            *(float4*)&bv[4] = *(const float4*)&Bs[k][tx * TN + 4];
#pragma unroll
            for (int i = 0; i < TM; i++)
#pragma unroll
                for (int j = 0; j < TN; j++)
                    acc[i][j] += a[i] * bv[j];
        }
        __syncthreads();
    }

    // Epilogue (scalar stores, bounds-checked on columns for O=1095 case)
#pragma unroll
    for (int i = 0; i < TM; i++) {
        int r = bm + ty * TM + i;
#pragma unroll
        for (int j = 0; j < TN; j++) {
            int cidx = bn + tx * TN + j;
            if (cidx < storeN) {
                float v = acc[i][j];
                if (bias) v += bias[cidx];
                C[(size_t)r * ldc + cidx] = v;
            }
        }
    }
}

// ---------------------------------------------------------------------------
// SRU recurrence: one thread per (b, d) channel, T sequential steps.
//   f = sigmoid(u1 + vf*c + bf); c = f*c + (1-f)*u0
//   r = sigmoid(u2 + vr*c + br); h = r*c + (1-r)*x
// Writes c_fin into the output buffer. Last layer reorders h to batch-major.
// ---------------------------------------------------------------------------
__global__ __launch_bounds__(256) void sru_kernel(
    const float* __restrict__ U, const float* __restrict__ hin,
    float* __restrict__ hout, const float* __restrict__ v,
    const float* __restrict__ bp, float* __restrict__ cfin, int reorder)
{
    int idx = blockIdx.x * blockDim.x + threadIdx.x;
    if (idx >= B_ * D_) return;
    int b = idx / D_;
    int d = idx % D_;

    const float vf = v[d], vr = v[D_ + d];
    const float bf = bp[d], br = bp[D_ + d];
    float c = 0.0f;

    for (int t = 0; t < T_; t++) {
        size_t row = (size_t)t * B_ + b;
        const float* u = U + row * N3_ + d;
        float u0 = u[0];
        float u1 = u[D_];
        float u2 = u[2 * D_];
        float xt = hin[row * D_ + d];

        float f = 1.0f / (1.0f + __expf(-(u1 + vf * c + bf)));
        c = f * c + (1.0f - f) * u0;
        float r = 1.0f / (1.0f + __expf(-(u2 + vr * c + br)));
        float ht = r * c + (1.0f - r) * xt;

        if (reorder) hout[((size_t)b * T_ + t) * D_ + d] = ht;
        else         hout[row * D_ + d] = ht;
    }
    cfin[(size_t)b * D_ + d] = c;
}

// ---------------------------------------------------------------------------
// Launcher
// ---------------------------------------------------------------------------
extern "C" void kernel_launch(void* const* d_in, const int* in_sizes, int n_in,
                              void* d_out, int out_size)
{
    const float* x     = (const float*)d_in[0];
    // d_in[1] = c (ignored by the reference model)
    const float* W1    = (const float*)d_in[2];
    const float* b1    = (const float*)d_in[3];
    const float* sru_W = (const float*)d_in[4];
    const float* sru_v = (const float*)d_in[5];
    const float* sru_b = (const float*)d_in[6];
    const float* W3    = (const float*)d_in[7];
    const float* b3    = (const float*)d_in[8];
    float* out = (float*)d_out;

    float *hP, *hordP, *UP, *W3pP;
    cudaGetSymbolAddress((void**)&hP,    g_h);
    cudaGetSymbolAddress((void**)&hordP, g_hord);
    cudaGetSymbolAddress((void**)&UP,    g_U);
    cudaGetSymbolAddress((void**)&W3pP,  g_W3p);

    // 1) Input projection -> g_h (time-major)
    proj_kernel<<<M_ / PROJ_ROWS, 256>>>(x, W1, b1);

    // 2) Pad W3 (overlaps nothing; independent)
    pad_w3_kernel<<<(D_ * OPAD + 255) / 256, 256>>>(W3);

    // 3) SRU layers
    for (int l = 0; l < L_; l++) {
        const float* Wl = sru_W + (size_t)l * D_ * N3_;
        dim3 grid(N3_ / BN, M_ / BM);
        sgemm_kernel<<<grid, 256>>>(hP, Wl, UP, N3_, D_, N3_, N3_, nullptr, N3_);

        const float* vl = sru_v + (size_t)l * 2 * D_;
        const float* bl = sru_b + (size_t)l * 2 * D_;
        float* cfin = out + Y_SIZE + (size_t)l * B_ * D_;
        int reorder = (l == L_ - 1) ? 1 : 0;
        float* hout = reorder ? hordP : hP;
        sru_kernel<<<(B_ * D_ + 255) / 256, 256>>>(UP, hP, hout, vl, bl, cfin, reorder);
    }

    // 4) Output GEMM: y = h_ord @ W3pad + b3, store only first O_ columns
    {
        dim3 grid(OPAD / BN, M_ / BM);
        sgemm_kernel<<<grid, 256>>>(hordP, W3pP, out, OPAD, D_, OPAD, O_, b3, O_);
    }
}

// round 4
// speedup vs baseline: 2.7225x; 2.7225x over previous
#include <cuda_runtime.h>
#include <cuda_bf16.h>
#include <cstdint>
#include <math.h>

// Problem dims
#define B_  64
#define T_  512
#define F_  20
#define D_  1024
#define O_  1095
#define L_  3
#define M_  (B_ * T_)        // 32768
#define N3_ (3 * D_)         // 3072
#define OPAD 1152
#define Y_SIZE ((size_t)M_ * O_)

// ---------------------------------------------------------------------------
// Scratch (static device globals)
// ---------------------------------------------------------------------------
__device__ float g_h[(size_t)M_ * D_];                    // fp32 hidden (time-major)
__device__ float g_U[(size_t)M_ * N3_];                   // gate pre-activations
__device__ __nv_bfloat16 g_Ah[(size_t)M_ * D_];           // hi split of A
__device__ __nv_bfloat16 g_Al[(size_t)M_ * D_];           // lo split of A
__device__ __nv_bfloat16 g_Wth[(size_t)L_ * N3_ * D_];    // sru_W^T hi  [l][n][k]
__device__ __nv_bfloat16 g_Wtl[(size_t)L_ * N3_ * D_];    // sru_W^T lo
__device__ __nv_bfloat16 g_W3th[(size_t)OPAD * D_];       // W3^T hi (zero padded)
__device__ __nv_bfloat16 g_W3tl[(size_t)OPAD * D_];       // W3^T lo

__device__ __forceinline__ uint32_t smem_to_u32(const void* p) {
    uint32_t a;
    asm("{ .reg .u64 t; cvta.to.shared.u64 t, %1; cvt.u32.u64 %0, t; }" : "=r"(a) : "l"(p));
    return a;
}

__device__ __forceinline__ void split_bf16(float v, __nv_bfloat16& hi, __nv_bfloat16& lo) {
    hi = __float2bfloat16(v);
    lo = __float2bfloat16(v - __bfloat162float(hi));
}

// ---------------------------------------------------------------------------
// Input projection -> g_h (fp32) + g_Ah/g_Al (bf16 splits), time-major
// ---------------------------------------------------------------------------
#define PROJ_ROWS 16
__global__ __launch_bounds__(256) void proj_kernel(
    const float* __restrict__ x, const float* __restrict__ W1,
    const float* __restrict__ b1)
{
    int r0 = blockIdx.x * PROJ_ROWS;
    __shared__ float xs[PROJ_ROWS][F_];
    for (int i = threadIdx.x; i < PROJ_ROWS * F_; i += blockDim.x) {
        int rr = i / F_, f = i % F_;
        int r = r0 + rr;
        int b = r % B_, t = r / B_;
        xs[rr][f] = x[((size_t)b * T_ + t) * F_ + f];
    }
    __syncthreads();
    for (int d = threadIdx.x; d < D_; d += blockDim.x) {
        float w[F_];
#pragma unroll
        for (int f = 0; f < F_; f++) w[f] = W1[f * D_ + d];
        float bb = b1[d];
#pragma unroll
        for (int rr = 0; rr < PROJ_ROWS; rr++) {
            float acc = bb;
#pragma unroll
            for (int f = 0; f < F_; f++) acc += xs[rr][f] * w[f];
            size_t o = (size_t)(r0 + rr) * D_ + d;
            g_h[o] = acc;
            __nv_bfloat16 hi, lo;
            split_bf16(acc, hi, lo);
            g_Ah[o] = hi;
            g_Al[o] = lo;
        }
    }
}

// ---------------------------------------------------------------------------
// Weight prep: transpose + hi/lo split. sru_W (L, K=D, N=3D) -> [l][n][k]
// ---------------------------------------------------------------------------
__global__ __launch_bounds__(256) void wprep_sru_kernel(const float* __restrict__ W)
{
    __shared__ float tile[32][33];
    int l = blockIdx.z;
    int n0 = blockIdx.x * 32, k0 = blockIdx.y * 32;
    const float* Wl = W + (size_t)l * D_ * N3_;
    int tx = threadIdx.x & 31, ty = threadIdx.x >> 5;
    for (int dy = ty; dy < 32; dy += 8)
        tile[dy][tx] = Wl[(size_t)(k0 + dy) * N3_ + n0 + tx];
    __syncthreads();
    __nv_bfloat16* oh = g_Wth + (size_t)l * N3_ * D_;
    __nv_bfloat16* ol = g_Wtl + (size_t)l * N3_ * D_;
    for (int dy = ty; dy < 32; dy += 8) {
        float v = tile[tx][dy];  // = W[k0+tx][n0+dy]
        __nv_bfloat16 hi, lo;
        split_bf16(v, hi, lo);
        size_t o = (size_t)(n0 + dy) * D_ + k0 + tx;
        oh[o] = hi;
        ol[o] = lo;
    }
}

__global__ __launch_bounds__(256) void wprep_w3_kernel(const float* __restrict__ W3)
{
    __shared__ float tile[32][33];
    int n0 = blockIdx.x * 32, k0 = blockIdx.y * 32;
    int tx = threadIdx.x & 31, ty = threadIdx.x >> 5;
    for (int dy = ty; dy < 32; dy += 8) {
        int n = n0 + tx;
        tile[dy][tx] = (n < O_) ? W3[(size_t)(k0 + dy) * O_ + n] : 0.0f;
    }
    __syncthreads();
    for (int dy = ty; dy < 32; dy += 8) {
        float v = tile[tx][dy];
        __nv_bfloat16 hi, lo;
        split_bf16(v, hi, lo);
        size_t o = (size_t)(n0 + dy) * D_ + k0 + tx;
        g_W3th[o] = hi;
        g_W3tl[o] = lo;
    }
}

// ---------------------------------------------------------------------------
// mma.sync bf16 GEMM with 3-term fp32-emulation split.
// C[128 x 128] per CTA. A: [M,K] bf16 hi/lo (K-major). B: [N,K] bf16 hi/lo.
// BK=64, cp.async double buffer, 8 warps each computing 32x64.
// SMEM tiles: 128 rows x 128 bytes, 16B-chunk XOR swizzle (c ^= row&7).
// ---------------------------------------------------------------------------
#define BKK 64
#define NCHUNK (D_ / BKK)        // 16
#define TILE_B (128 * 128)       // 16384 bytes per tile
#define STAGE_B (4 * TILE_B)     // 65536
#define GEMM_SMEM (2 * STAGE_B)  // 131072

#define CP_ASYNC16(s, g) \
    asm volatile("cp.async.cg.shared.global [%0], [%1], 16;" :: "r"(s), "l"(g))
#define CP_COMMIT() asm volatile("cp.async.commit_group;" ::: "memory")
#define CP_WAIT(n)  asm volatile("cp.async.wait_group %0;" :: "n"(n) : "memory")

#define LDSM_X4(r0, r1, r2, r3, a) \
    asm volatile("ldmatrix.sync.aligned.m8n8.x4.shared.b16 {%0,%1,%2,%3}, [%4];" \
        : "=r"(r0), "=r"(r1), "=r"(r2), "=r"(r3) : "r"(a))

#define MMA16816(c, a, b) \
    asm volatile("mma.sync.aligned.m16n8k16.row.col.f32.bf16.bf16.f32 " \
        "{%0,%1,%2,%3}, {%4,%5,%6,%7}, {%8,%9}, {%0,%1,%2,%3};" \
        : "+f"((c)[0]), "+f"((c)[1]), "+f"((c)[2]), "+f"((c)[3]) \
        : "r"((a)[0]), "r"((a)[1]), "r"((a)[2]), "r"((a)[3]), "r"((b)[0]), "r"((b)[1]))

// load one 128x64 bf16 tile (row0 = m0 or n0) into swizzled smem
__device__ __forceinline__ void load_tile(uint32_t sbase, const __nv_bfloat16* g,
                                          int row0, int kk) {
    const int tid = threadIdx.x;
#pragma unroll
    for (int j = 0; j < 4; j++) {
        int i = tid + 256 * j;         // 0..1023
        int row = i >> 3;
        int c = i & 7;
        uint32_t s = sbase + row * 128 + ((c ^ (row & 7)) << 4);
        const void* gp = g + (size_t)(row0 + row) * D_ + kk + c * 8;
        CP_ASYNC16(s, gp);
    }
}

__global__ __launch_bounds__(256, 1) void gemm_kernel(
    const __nv_bfloat16* __restrict__ Ah, const __nv_bfloat16* __restrict__ Al,
    const __nv_bfloat16* __restrict__ Bh, const __nv_bfloat16* __restrict__ Bl,
    float* __restrict__ C, int ldc, int nmax, const float* __restrict__ bias)
{
    extern __shared__ char smem[];
    const uint32_t sbase = smem_to_u32(smem);
    const int tid = threadIdx.x;
    const int lane = tid & 31;
    const int wid = tid >> 5;
    const int wm = wid & 3;          // 4 warps along M -> 32 rows each
    const int wn = wid >> 2;         // 2 warps along N -> 64 cols each
    const int m0 = blockIdx.y * 128;
    const int n0 = blockIdx.x * 128;
    const bool vec = ((ldc & 1) == 0);   // float2 stores only if rows stay 8B-aligned

    float acc[2][8][4];
#pragma unroll
    for (int i = 0; i < 2; i++)
#pragma unroll
        for (int j = 0; j < 8; j++)
#pragma unroll
            for (int q = 0; q < 4; q++) acc[i][j][q] = 0.0f;

    // prologue: stages 0 and 1
#pragma unroll
    for (int p = 0; p < 2; p++) {
        uint32_t st = sbase + p * STAGE_B;
        load_tile(st + 0 * TILE_B, Ah, m0, p * BKK);
        load_tile(st + 1 * TILE_B, Al, m0, p * BKK);
        load_tile(st + 2 * TILE_B, Bh, n0, p * BKK);
        load_tile(st + 3 * TILE_B, Bl, n0, p * BKK);
        CP_COMMIT();
    }

    // precomputed ldmatrix row/half components (per thread)
    const int a_roff = (lane & 7) + ((lane >> 3) & 1) * 8;  // row within 16
    const int a_half = (lane >> 4) & 1;
    const int b_roff = (lane & 7) + ((lane >> 4) & 1) * 8;
    const int b_half = (lane >> 3) & 1;

    for (int k = 0; k < NCHUNK; k++) {
        if (k < NCHUNK - 1) CP_WAIT(1); else CP_WAIT(0);
        __syncthreads();

        const uint32_t st = sbase + (k & 1) * STAGE_B;
        const uint32_t aAh = st, aAl = st + TILE_B, aBh = st + 2 * TILE_B, aBl = st + 3 * TILE_B;

#pragma unroll
        for (int ks = 0; ks < 4; ks++) {
            uint32_t ahf[2][4], alf[2][4], bhf[8][2], blf[8][2];
            // A fragments (hi, lo) for 2 m16 atoms
#pragma unroll
            for (int mi = 0; mi < 2; mi++) {
                int row = wm * 32 + mi * 16 + a_roff;
                int c = (ks * 2 + a_half) ^ (row & 7);
                uint32_t off = row * 128 + (c << 4);
                LDSM_X4(ahf[mi][0], ahf[mi][1], ahf[mi][2], ahf[mi][3], aAh + off);
                LDSM_X4(alf[mi][0], alf[mi][1], alf[mi][2], alf[mi][3], aAl + off);
            }
            // B fragments (hi, lo) for 8 n8 atoms (4 x4-loads each)
#pragma unroll
            for (int g = 0; g < 4; g++) {
                int row = wn * 64 + g * 16 + b_roff;
                int c = (ks * 2 + b_half) ^ (row & 7);
                uint32_t off = row * 128 + (c << 4);
                uint32_t r0, r1, r2, r3;
                LDSM_X4(r0, r1, r2, r3, aBh + off);
                bhf[g * 2][0] = r0; bhf[g * 2][1] = r1;
                bhf[g * 2 + 1][0] = r2; bhf[g * 2 + 1][1] = r3;
                LDSM_X4(r0, r1, r2, r3, aBl + off);
                blf[g * 2][0] = r0; blf[g * 2][1] = r1;
                blf[g * 2 + 1][0] = r2; blf[g * 2 + 1][1] = r3;
            }
            // 3-term MMAs
#pragma unroll
            for (int mi = 0; mi < 2; mi++)
#pragma unroll
                for (int ni = 0; ni < 8; ni++) {
                    MMA16816(acc[mi][ni], ahf[mi], bhf[ni]);
                    MMA16816(acc[mi][ni], alf[mi], bhf[ni]);
                    MMA16816(acc[mi][ni], ahf[mi], blf[ni]);
                }
        }

        __syncthreads();
        if (k + 2 < NCHUNK) {
            uint32_t st2 = sbase + (k & 1) * STAGE_B;
            const int kk = (k + 2) * BKK;
            load_tile(st2 + 0 * TILE_B, Ah, m0, kk);
            load_tile(st2 + 1 * TILE_B, Al, m0, kk);
            load_tile(st2 + 2 * TILE_B, Bh, n0, kk);
            load_tile(st2 + 3 * TILE_B, Bl, n0, kk);
            CP_COMMIT();
        } else {
            CP_COMMIT();  // keep wait_group counts consistent
        }
    }

    // epilogue: c frag -> global. float2 only when ldc keeps rows 8B-aligned.
#pragma unroll
    for (int ni = 0; ni < 8; ni++) {
        int col = n0 + wn * 64 + ni * 8 + (lane & 3) * 2;
        float bv0 = 0.f, bv1 = 0.f;
        if (bias) {
            if (col < nmax)     bv0 = bias[col];
            if (col + 1 < nmax) bv1 = bias[col + 1];
        }
#pragma unroll
        for (int mi = 0; mi < 2; mi++) {
            int row = m0 + wm * 32 + mi * 16 + (lane >> 2);
            float* p0 = C + (size_t)row * ldc + col;
            float* p1 = C + (size_t)(row + 8) * ldc + col;
            if (vec && col + 1 < nmax) {
                *(float2*)p0 = make_float2(acc[mi][ni][0] + bv0, acc[mi][ni][1] + bv1);
                *(float2*)p1 = make_float2(acc[mi][ni][2] + bv0, acc[mi][ni][3] + bv1);
            } else {
                if (col < nmax) {
                    p0[0] = acc[mi][ni][0] + bv0;
                    p1[0] = acc[mi][ni][2] + bv0;
                }
                if (col + 1 < nmax) {
                    p0[1] = acc[mi][ni][1] + bv1;
                    p1[1] = acc[mi][ni][3] + bv1;
                }
            }
        }
    }
}

// ---------------------------------------------------------------------------
// SRU recurrence (prefetched), emits fp32 h + bf16 splits; c_fin -> out
// ---------------------------------------------------------------------------
__global__ __launch_bounds__(256) void sru_kernel(
    const float* __restrict__ U, const float* __restrict__ hin,
    float* __restrict__ hfp, __nv_bfloat16* __restrict__ ah,
    __nv_bfloat16* __restrict__ al, const float* __restrict__ v,
    const float* __restrict__ bp, float* __restrict__ cfin, int last)
{
    int idx = blockIdx.x * blockDim.x + threadIdx.x;
    int b = idx / D_, d = idx % D_;

    const float vf = v[d], vr = v[D_ + d];
    const float bf = bp[d], br = bp[D_ + d];
    float c = 0.0f;

    const size_t uoff = (size_t)b * N3_ + d;
    const size_t hoff = (size_t)b * D_ + d;
    const size_t ustep = (size_t)B_ * N3_;
    const size_t hstep = (size_t)B_ * D_;

    float u0 = __ldcs(U + uoff), u1 = __ldcs(U + uoff + D_), u2 = __ldcs(U + uoff + 2 * D_);
    float xt = __ldcs(hin + hoff);

    for (int t = 0; t < T_; t++) {
        float nu0 = 0.f, nu1 = 0.f, nu2 = 0.f, nx = 0.f;
        if (t + 1 < T_) {
            const float* up = U + uoff + (size_t)(t + 1) * ustep;
            nu0 = __ldcs(up);
            nu1 = __ldcs(up + D_);
            nu2 = __ldcs(up + 2 * D_);
            nx  = __ldcs(hin + hoff + (size_t)(t + 1) * hstep);
        }
        float f = 1.0f / (1.0f + __expf(-(u1 + vf * c + bf)));
        c = f * c + (1.0f - f) * u0;
        float rr = 1.0f / (1.0f + __expf(-(u2 + vr * c + br)));
        float ht = rr * c + (1.0f - rr) * xt;

        __nv_bfloat16 hi, lo;
        split_bf16(ht, hi, lo);
        if (last) {
            size_t o = ((size_t)b * T_ + t) * D_ + d;  // batch-major for final GEMM
            ah[o] = hi;
            al[o] = lo;
        } else {
            size_t o = hoff + (size_t)t * hstep;       // time-major
            hfp[o] = ht;
            ah[o] = hi;
            al[o] = lo;
        }
        u0 = nu0; u1 = nu1; u2 = nu2; xt = nx;
    }
    cfin[hoff] = c;
}

// ---------------------------------------------------------------------------
// Launcher
// ---------------------------------------------------------------------------
extern "C" void kernel_launch(void* const* d_in, const int* in_sizes, int n_in,
                              void* d_out, int out_size)
{
    const float* x     = (const float*)d_in[0];
    const float* W1    = (const float*)d_in[2];
    const float* b1    = (const float*)d_in[3];
    const float* sru_W = (const float*)d_in[4];
    const float* sru_v = (const float*)d_in[5];
    const float* sru_b = (const float*)d_in[6];
    const float* W3    = (const float*)d_in[7];
    const float* b3    = (const float*)d_in[8];
    float* out = (float*)d_out;

    float *hP, *UP;
    __nv_bfloat16 *AhP, *AlP, *WthP, *WtlP, *W3thP, *W3tlP;
    cudaGetSymbolAddress((void**)&hP, g_h);
    cudaGetSymbolAddress((void**)&UP, g_U);
    cudaGetSymbolAddress((void**)&AhP, g_Ah);
    cudaGetSymbolAddress((void**)&AlP, g_Al);
    cudaGetSymbolAddress((void**)&WthP, g_Wth);
    cudaGetSymbolAddress((void**)&WtlP, g_Wtl);
    cudaGetSymbolAddress((void**)&W3thP, g_W3th);
    cudaGetSymbolAddress((void**)&W3tlP, g_W3tl);

    cudaFuncSetAttribute(gemm_kernel, cudaFuncAttributeMaxDynamicSharedMemorySize, GEMM_SMEM);

    // Weight prep
    {
        dim3 g(N3_ / 32, D_ / 32, L_);
        wprep_sru_kernel<<<g, 256>>>(sru_W);
        dim3 g3(OPAD / 32, D_ / 32, 1);
        wprep_w3_kernel<<<g3, 256>>>(W3);
    }

    // Input projection
    proj_kernel<<<M_ / PROJ_ROWS, 256>>>(x, W1, b1);

    // SRU layers
    for (int l = 0; l < L_; l++) {
        const __nv_bfloat16* Bh = WthP + (size_t)l * N3_ * D_;
        const __nv_bfloat16* Bl = WtlP + (size_t)l * N3_ * D_;
        dim3 grid(N3_ / 128, M_ / 128);
        gemm_kernel<<<grid, 256, GEMM_SMEM>>>(AhP, AlP, Bh, Bl, UP, N3_, N3_, nullptr);

        const float* vl = sru_v + (size_t)l * 2 * D_;
        const float* bl = sru_b + (size_t)l * 2 * D_;
        float* cfin = out + Y_SIZE + (size_t)l * B_ * D_;
        int last = (l == L_ - 1) ? 1 : 0;
        sru_kernel<<<(B_ * D_) / 256, 256>>>(UP, hP, hP, AhP, AlP, vl, bl, cfin, last);
    }

    // Output GEMM: y = h @ W3 + b3
    {
        dim3 grid(OPAD / 128, M_ / 128);
        gemm_kernel<<<grid, 256, GEMM_SMEM>>>(AhP, AlP, W3thP, W3tlP, out, O_, O_, b3);
    }
}

// round 5
// speedup vs baseline: 3.9850x; 1.4637x over previous
#include <cuda_runtime.h>
#include <cuda_fp16.h>
#include <cstdint>
#include <math.h>

// Problem dims
#define B_  64
#define T_  512
#define F_  20
#define D_  1024
#define O_  1095
#define L_  3
#define M_  (B_ * T_)        // 32768
#define N3_ (3 * D_)         // 3072
#define OPAD 1152
#define Y_SIZE ((size_t)M_ * O_)

// ---------------------------------------------------------------------------
// Scratch (static device globals)
// ---------------------------------------------------------------------------
__device__ float g_h[(size_t)M_ * D_];                // fp32 hidden (time-major)
__device__ float g_U[(size_t)M_ * N3_];               // gate pre-activations
__device__ __half g_Ah[(size_t)M_ * D_];              // hi split of A (fp16)
__device__ __half g_Al[(size_t)M_ * D_];              // lo split of A (fp16)
__device__ __half g_Wt[(size_t)L_ * N3_ * D_];        // sru_W^T fp16  [l][n][k]
__device__ __half g_W3t[(size_t)OPAD * D_];           // W3^T fp16 (zero padded)

__device__ __forceinline__ uint32_t smem_to_u32(const void* p) {
    uint32_t a;
    asm("{ .reg .u64 t; cvta.to.shared.u64 t, %1; cvt.u32.u64 %0, t; }" : "=r"(a) : "l"(p));
    return a;
}

__device__ __forceinline__ void split_fp16(float v, __half& hi, __half& lo) {
    hi = __float2half(v);
    lo = __float2half(v - __half2float(hi));
}

// ---------------------------------------------------------------------------
// Input projection -> g_h (fp32) + g_Ah/g_Al (fp16 splits), time-major
// ---------------------------------------------------------------------------
#define PROJ_ROWS 16
__global__ __launch_bounds__(256) void proj_kernel(
    const float* __restrict__ x, const float* __restrict__ W1,
    const float* __restrict__ b1)
{
    int r0 = blockIdx.x * PROJ_ROWS;
    __shared__ float xs[PROJ_ROWS][F_];
    for (int i = threadIdx.x; i < PROJ_ROWS * F_; i += blockDim.x) {
        int rr = i / F_, f = i % F_;
        int r = r0 + rr;
        int b = r % B_, t = r / B_;
        xs[rr][f] = x[((size_t)b * T_ + t) * F_ + f];
    }
    __syncthreads();
    for (int d = threadIdx.x; d < D_; d += blockDim.x) {
        float w[F_];
#pragma unroll
        for (int f = 0; f < F_; f++) w[f] = W1[f * D_ + d];
        float bb = b1[d];
#pragma unroll
        for (int rr = 0; rr < PROJ_ROWS; rr++) {
            float acc = bb;
#pragma unroll
            for (int f = 0; f < F_; f++) acc += xs[rr][f] * w[f];
            size_t o = (size_t)(r0 + rr) * D_ + d;
            g_h[o] = acc;
            __half hi, lo;
            split_fp16(acc, hi, lo);
            g_Ah[o] = hi;
            g_Al[o] = lo;
        }
    }
}

// ---------------------------------------------------------------------------
// Weight prep: transpose + fp16 round. sru_W (L, K=D, N=3D) -> [l][n][k]
// ---------------------------------------------------------------------------
__global__ __launch_bounds__(256) void wprep_sru_kernel(const float* __restrict__ W)
{
    __shared__ float tile[32][33];
    int l = blockIdx.z;
    int n0 = blockIdx.x * 32, k0 = blockIdx.y * 32;
    const float* Wl = W + (size_t)l * D_ * N3_;
    int tx = threadIdx.x & 31, ty = threadIdx.x >> 5;
    for (int dy = ty; dy < 32; dy += 8)
        tile[dy][tx] = Wl[(size_t)(k0 + dy) * N3_ + n0 + tx];
    __syncthreads();
    __half* oh = g_Wt + (size_t)l * N3_ * D_;
    for (int dy = ty; dy < 32; dy += 8) {
        float v = tile[tx][dy];  // = W[k0+tx][n0+dy]
        oh[(size_t)(n0 + dy) * D_ + k0 + tx] = __float2half(v);
    }
}

__global__ __launch_bounds__(256) void wprep_w3_kernel(const float* __restrict__ W3)
{
    __shared__ float tile[32][33];
    int n0 = blockIdx.x * 32, k0 = blockIdx.y * 32;
    int tx = threadIdx.x & 31, ty = threadIdx.x >> 5;
    for (int dy = ty; dy < 32; dy += 8) {
        int n = n0 + tx;
        tile[dy][tx] = (n < O_) ? W3[(size_t)(k0 + dy) * O_ + n] : 0.0f;
    }
    __syncthreads();
    for (int dy = ty; dy < 32; dy += 8) {
        float v = tile[tx][dy];
        g_W3t[(size_t)(n0 + dy) * D_ + k0 + tx] = __float2half(v);
    }
}

// ---------------------------------------------------------------------------
// mma.sync fp16 GEMM, asymmetric 2-term split: C = (Ah + Al) * Bh.
// C[128 x 128] per CTA. A: [M,K] fp16 hi/lo (K-major). B: [N,K] fp16.
// BK=64, cp.async double buffer, 3 tiles/stage (96KB), 2 CTAs/SM target.
// SMEM tiles: 128 rows x 128 bytes, 16B-chunk XOR swizzle (c ^= row&7).
// ---------------------------------------------------------------------------
#define BKK 64
#define NCHUNK (D_ / BKK)        // 16
#define TILE_B (128 * 128)       // 16384 bytes per tile
#define STAGE_B (3 * TILE_B)     // 49152
#define GEMM_SMEM (2 * STAGE_B)  // 98304

#define CP_ASYNC16(s, g) \
    asm volatile("cp.async.cg.shared.global [%0], [%1], 16;" :: "r"(s), "l"(g))
#define CP_COMMIT() asm volatile("cp.async.commit_group;" ::: "memory")
#define CP_WAIT(n)  asm volatile("cp.async.wait_group %0;" :: "n"(n) : "memory")

#define LDSM_X4(r0, r1, r2, r3, a) \
    asm volatile("ldmatrix.sync.aligned.m8n8.x4.shared.b16 {%0,%1,%2,%3}, [%4];" \
        : "=r"(r0), "=r"(r1), "=r"(r2), "=r"(r3) : "r"(a))

#define MMA16816(c, a, b) \
    asm volatile("mma.sync.aligned.m16n8k16.row.col.f32.f16.f16.f32 " \
        "{%0,%1,%2,%3}, {%4,%5,%6,%7}, {%8,%9}, {%0,%1,%2,%3};" \
        : "+f"((c)[0]), "+f"((c)[1]), "+f"((c)[2]), "+f"((c)[3]) \
        : "r"((a)[0]), "r"((a)[1]), "r"((a)[2]), "r"((a)[3]), "r"((b)[0]), "r"((b)[1]))

// load one 128x64 fp16 tile (row0 = m0 or n0) into swizzled smem
__device__ __forceinline__ void load_tile(uint32_t sbase, const __half* g,
                                          int row0, int kk) {
    const int tid = threadIdx.x;
#pragma unroll
    for (int j = 0; j < 4; j++) {
        int i = tid + 256 * j;         // 0..1023
        int row = i >> 3;
        int c = i & 7;
        uint32_t s = sbase + row * 128 + ((c ^ (row & 7)) << 4);
        const void* gp = g + (size_t)(row0 + row) * D_ + kk + c * 8;
        CP_ASYNC16(s, gp);
    }
}

__global__ __launch_bounds__(256, 2) void gemm_kernel(
    const __half* __restrict__ Ah, const __half* __restrict__ Al,
    const __half* __restrict__ Bh,
    float* __restrict__ C, int ldc, int nmax, const float* __restrict__ bias)
{
    extern __shared__ char smem[];
    const uint32_t sbase = smem_to_u32(smem);
    const int tid = threadIdx.x;
    const int lane = tid & 31;
    const int wid = tid >> 5;
    const int wm = wid & 3;          // 4 warps along M -> 32 rows each
    const int wn = wid >> 2;         // 2 warps along N -> 64 cols each
    const int m0 = blockIdx.y * 128;
    const int n0 = blockIdx.x * 128;
    const bool vec = ((ldc & 1) == 0);   // float2 stores only if rows stay 8B-aligned

    float acc[2][8][4];
#pragma unroll
    for (int i = 0; i < 2; i++)
#pragma unroll
        for (int j = 0; j < 8; j++)
#pragma unroll
            for (int q = 0; q < 4; q++) acc[i][j][q] = 0.0f;

    // prologue: stages 0 and 1
#pragma unroll
    for (int p = 0; p < 2; p++) {
        uint32_t st = sbase + p * STAGE_B;
        load_tile(st + 0 * TILE_B, Ah, m0, p * BKK);
        load_tile(st + 1 * TILE_B, Al, m0, p * BKK);
        load_tile(st + 2 * TILE_B, Bh, n0, p * BKK);
        CP_COMMIT();
    }

    // precomputed ldmatrix row/half components (per thread)
    const int a_roff = (lane & 7) + ((lane >> 3) & 1) * 8;  // row within 16
    const int a_half = (lane >> 4) & 1;
    const int b_roff = (lane & 7) + ((lane >> 4) & 1) * 8;
    const int b_half = (lane >> 3) & 1;

    for (int k = 0; k < NCHUNK; k++) {
        if (k < NCHUNK - 1) CP_WAIT(1); else CP_WAIT(0);
        __syncthreads();

        const uint32_t st = sbase + (k & 1) * STAGE_B;
        const uint32_t aAh = st, aAl = st + TILE_B, aBh = st + 2 * TILE_B;

#pragma unroll
        for (int ks = 0; ks < 4; ks++) {
            uint32_t ahf[2][4], alf[2][4], bhf[8][2];
            // A fragments (hi, lo) for 2 m16 atoms
#pragma unroll
            for (int mi = 0; mi < 2; mi++) {
                int row = wm * 32 + mi * 16 + a_roff;
                int c = (ks * 2 + a_half) ^ (row & 7);
                uint32_t off = row * 128 + (c << 4);
                LDSM_X4(ahf[mi][0], ahf[mi][1], ahf[mi][2], ahf[mi][3], aAh + off);
                LDSM_X4(alf[mi][0], alf[mi][1], alf[mi][2], alf[mi][3], aAl + off);
            }
            // B fragments for 8 n8 atoms (4 x4-loads)
#pragma unroll
            for (int g = 0; g < 4; g++) {
                int row = wn * 64 + g * 16 + b_roff;
                int c = (ks * 2 + b_half) ^ (row & 7);
                uint32_t off = row * 128 + (c << 4);
                uint32_t r0, r1, r2, r3;
                LDSM_X4(r0, r1, r2, r3, aBh + off);
                bhf[g * 2][0] = r0; bhf[g * 2][1] = r1;
                bhf[g * 2 + 1][0] = r2; bhf[g * 2 + 1][1] = r3;
            }
            // 2-term MMAs
#pragma unroll
            for (int mi = 0; mi < 2; mi++)
#pragma unroll
                for (int ni = 0; ni < 8; ni++) {
                    MMA16816(acc[mi][ni], ahf[mi], bhf[ni]);
                    MMA16816(acc[mi][ni], alf[mi], bhf[ni]);
                }
        }

        __syncthreads();
        if (k + 2 < NCHUNK) {
            uint32_t st2 = sbase + (k & 1) * STAGE_B;
            const int kk = (k + 2) * BKK;
            load_tile(st2 + 0 * TILE_B, Ah, m0, kk);
            load_tile(st2 + 1 * TILE_B, Al, m0, kk);
            load_tile(st2 + 2 * TILE_B, Bh, n0, kk);
            CP_COMMIT();
        } else {
            CP_COMMIT();  // keep wait_group counts consistent
        }
    }

    // epilogue: c frag -> global. float2 only when ldc keeps rows 8B-aligned.
#pragma unroll
    for (int ni = 0; ni < 8; ni++) {
        int col = n0 + wn * 64 + ni * 8 + (lane & 3) * 2;
        float bv0 = 0.f, bv1 = 0.f;
        if (bias) {
            if (col < nmax)     bv0 = bias[col];
            if (col + 1 < nmax) bv1 = bias[col + 1];
        }
#pragma unroll
        for (int mi = 0; mi < 2; mi++) {
            int row = m0 + wm * 32 + mi * 16 + (lane >> 2);
            float* p0 = C + (size_t)row * ldc + col;
            float* p1 = C + (size_t)(row + 8) * ldc + col;
            if (vec && col + 1 < nmax) {
                *(float2*)p0 = make_float2(acc[mi][ni][0] + bv0, acc[mi][ni][1] + bv1);
                *(float2*)p1 = make_float2(acc[mi][ni][2] + bv0, acc[mi][ni][3] + bv1);
            } else {
                if (col < nmax) {
                    p0[0] = acc[mi][ni][0] + bv0;
                    p1[0] = acc[mi][ni][2] + bv0;
                }
                if (col + 1 < nmax) {
                    p0[1] = acc[mi][ni][1] + bv1;
                    p1[1] = acc[mi][ni][3] + bv1;
                }
            }
        }
    }
}

// ---------------------------------------------------------------------------
// SRU recurrence (prefetched), emits fp32 h + fp16 splits; c_fin -> out
// ---------------------------------------------------------------------------
__global__ __launch_bounds__(256) void sru_kernel(
    const float* __restrict__ U, const float* __restrict__ hin,
    float* __restrict__ hfp, __half* __restrict__ ah,
    __half* __restrict__ al, const float* __restrict__ v,
    const float* __restrict__ bp, float* __restrict__ cfin, int last)
{
    int idx = blockIdx.x * blockDim.x + threadIdx.x;
    int b = idx / D_, d = idx % D_;

    const float vf = v[d], vr = v[D_ + d];
    const float bf = bp[d], br = bp[D_ + d];
    float c = 0.0f;

    const size_t uoff = (size_t)b * N3_ + d;
    const size_t hoff = (size_t)b * D_ + d;
    const size_t ustep = (size_t)B_ * N3_;
    const size_t hstep = (size_t)B_ * D_;

    float u0 = __ldcs(U + uoff), u1 = __ldcs(U + uoff + D_), u2 = __ldcs(U + uoff + 2 * D_);
    float xt = __ldcs(hin + hoff);

    for (int t = 0; t < T_; t++) {
        float nu0 = 0.f, nu1 = 0.f, nu2 = 0.f, nx = 0.f;
        if (t + 1 < T_) {
            const float* up = U + uoff + (size_t)(t + 1) * ustep;
            nu0 = __ldcs(up);
            nu1 = __ldcs(up + D_);
            nu2 = __ldcs(up + 2 * D_);
            nx  = __ldcs(hin + hoff + (size_t)(t + 1) * hstep);
        }
        float f = 1.0f / (1.0f + __expf(-(u1 + vf * c + bf)));
        c = f * c + (1.0f - f) * u0;
        float rr = 1.0f / (1.0f + __expf(-(u2 + vr * c + br)));
        float ht = rr * c + (1.0f - rr) * xt;

        __half hi, lo;
        split_fp16(ht, hi, lo);
        if (last) {
            size_t o = ((size_t)b * T_ + t) * D_ + d;  // batch-major for final GEMM
            ah[o] = hi;
            al[o] = lo;
        } else {
            size_t o = hoff + (size_t)t * hstep;       // time-major
            hfp[o] = ht;
            ah[o] = hi;
            al[o] = lo;
        }
        u0 = nu0; u1 = nu1; u2 = nu2; xt = nx;
    }
    cfin[hoff] = c;
}

// ---------------------------------------------------------------------------
// Launcher
// ---------------------------------------------------------------------------
extern "C" void kernel_launch(void* const* d_in, const int* in_sizes, int n_in,
                              void* d_out, int out_size)
{
    const float* x     = (const float*)d_in[0];
    const float* W1    = (const float*)d_in[2];
    const float* b1    = (const float*)d_in[3];
    const float* sru_W = (const float*)d_in[4];
    const float* sru_v = (const float*)d_in[5];
    const float* sru_b = (const float*)d_in[6];
    const float* W3    = (const float*)d_in[7];
    const float* b3    = (const float*)d_in[8];
    float* out = (float*)d_out;

    float *hP, *UP;
    __half *AhP, *AlP, *WtP, *W3tP;
    cudaGetSymbolAddress((void**)&hP, g_h);
    cudaGetSymbolAddress((void**)&UP, g_U);
    cudaGetSymbolAddress((void**)&AhP, g_Ah);
    cudaGetSymbolAddress((void**)&AlP, g_Al);
    cudaGetSymbolAddress((void**)&WtP, g_Wt);
    cudaGetSymbolAddress((void**)&W3tP, g_W3t);

    cudaFuncSetAttribute(gemm_kernel, cudaFuncAttributeMaxDynamicSharedMemorySize, GEMM_SMEM);

    // Weight prep
    {
        dim3 g(N3_ / 32, D_ / 32, L_);
        wprep_sru_kernel<<<g, 256>>>(sru_W);
        dim3 g3(OPAD / 32, D_ / 32, 1);
        wprep_w3_kernel<<<g3, 256>>>(W3);
    }

    // Input projection
    proj_kernel<<<M_ / PROJ_ROWS, 256>>>(x, W1, b1);

    // SRU layers
    for (int l = 0; l < L_; l++) {
        const __half* Bh = WtP + (size_t)l * N3_ * D_;
        dim3 grid(N3_ / 128, M_ / 128);
        gemm_kernel<<<grid, 256, GEMM_SMEM>>>(AhP, AlP, Bh, UP, N3_, N3_, nullptr);

        const float* vl = sru_v + (size_t)l * 2 * D_;
        const float* bl = sru_b + (size_t)l * 2 * D_;
        float* cfin = out + Y_SIZE + (size_t)l * B_ * D_;
        int last = (l == L_ - 1) ? 1 : 0;
        sru_kernel<<<(B_ * D_) / 256, 256>>>(UP, hP, hP, AhP, AlP, vl, bl, cfin, last);
    }

    // Output GEMM: y = h @ W3 + b3
    {
        dim3 grid(OPAD / 128, M_ / 128);
        gemm_kernel<<<grid, 256, GEMM_SMEM>>>(AhP, AlP, W3tP, out, O_, O_, b3);
    }
}

// round 6
// speedup vs baseline: 6.0541x; 1.5192x over previous
#include <cuda_runtime.h>
#include <cuda_fp16.h>
#include <cstdint>
#include <math.h>

// Problem dims
#define B_  64
#define T_  512
#define F_  20
#define D_  1024
#define O_  1095
#define L_  3
#define M_  (B_ * T_)        // 32768
#define N3_ (3 * D_)         // 3072
#define OPAD 1152
#define Y_SIZE ((size_t)M_ * O_)

// ---------------------------------------------------------------------------
// Scratch (static device globals)
// ---------------------------------------------------------------------------
__device__ float  g_U0[(size_t)M_ * D_];          // u0 gate pre-activation (fp32)
__device__ __half g_U12[(size_t)M_ * 2 * D_];     // u1|u2 (fp16), [row][2048]
__device__ __half g_A[(size_t)M_ * D_];           // fp16 hidden (time-major)
__device__ __half g_Aord[(size_t)M_ * D_];        // fp16 hidden (batch-major, last layer)
__device__ __half g_Wt[(size_t)L_ * N3_ * D_];    // sru_W^T fp16  [l][n][k]
__device__ __half g_W3t[(size_t)OPAD * D_];       // W3^T fp16 (zero padded)

__device__ __forceinline__ uint32_t smem_to_u32(const void* p) {
    uint32_t a;
    asm("{ .reg .u64 t; cvta.to.shared.u64 t, %1; cvt.u32.u64 %0, t; }" : "=r"(a) : "l"(p));
    return a;
}

// ---------------------------------------------------------------------------
// Input projection -> g_A (fp16), time-major
// ---------------------------------------------------------------------------
#define PROJ_ROWS 16
__global__ __launch_bounds__(256) void proj_kernel(
    const float* __restrict__ x, const float* __restrict__ W1,
    const float* __restrict__ b1)
{
    int r0 = blockIdx.x * PROJ_ROWS;
    __shared__ float xs[PROJ_ROWS][F_];
    for (int i = threadIdx.x; i < PROJ_ROWS * F_; i += blockDim.x) {
        int rr = i / F_, f = i % F_;
        int r = r0 + rr;
        int b = r % B_, t = r / B_;
        xs[rr][f] = x[((size_t)b * T_ + t) * F_ + f];
    }
    __syncthreads();
    for (int d = threadIdx.x; d < D_; d += blockDim.x) {
        float w[F_];
#pragma unroll
        for (int f = 0; f < F_; f++) w[f] = W1[f * D_ + d];
        float bb = b1[d];
#pragma unroll
        for (int rr = 0; rr < PROJ_ROWS; rr++) {
            float acc = bb;
#pragma unroll
            for (int f = 0; f < F_; f++) acc += xs[rr][f] * w[f];
            g_A[(size_t)(r0 + rr) * D_ + d] = __float2half(acc);
        }
    }
}

// ---------------------------------------------------------------------------
// Weight prep: transpose + fp16 round. sru_W (L, K=D, N=3D) -> [l][n][k]
// ---------------------------------------------------------------------------
__global__ __launch_bounds__(256) void wprep_sru_kernel(const float* __restrict__ W)
{
    __shared__ float tile[32][33];
    int l = blockIdx.z;
    int n0 = blockIdx.x * 32, k0 = blockIdx.y * 32;
    const float* Wl = W + (size_t)l * D_ * N3_;
    int tx = threadIdx.x & 31, ty = threadIdx.x >> 5;
    for (int dy = ty; dy < 32; dy += 8)
        tile[dy][tx] = Wl[(size_t)(k0 + dy) * N3_ + n0 + tx];
    __syncthreads();
    __half* oh = g_Wt + (size_t)l * N3_ * D_;
    for (int dy = ty; dy < 32; dy += 8)
        oh[(size_t)(n0 + dy) * D_ + k0 + tx] = __float2half(tile[tx][dy]);
}

__global__ __launch_bounds__(256) void wprep_w3_kernel(const float* __restrict__ W3)
{
    __shared__ float tile[32][33];
    int n0 = blockIdx.x * 32, k0 = blockIdx.y * 32;
    int tx = threadIdx.x & 31, ty = threadIdx.x >> 5;
    for (int dy = ty; dy < 32; dy += 8) {
        int n = n0 + tx;
        tile[dy][tx] = (n < O_) ? W3[(size_t)(k0 + dy) * O_ + n] : 0.0f;
    }
    __syncthreads();
    for (int dy = ty; dy < 32; dy += 8)
        g_W3t[(size_t)(n0 + dy) * D_ + k0 + tx] = __float2half(tile[tx][dy]);
}

// ---------------------------------------------------------------------------
// mma.sync fp16 GEMM (single term). C[128 x 128] per CTA.
// A: [M,K] fp16 (K-major). B: [N,K] fp16. BK=64, 3-stage cp.async pipeline.
// SMEM tiles: 128 rows x 128 bytes, 16B-chunk XOR swizzle (c ^= row&7).
// SRU mode (U0 != null): u0 cols -> fp32 U0, u1/u2 cols -> fp16 U12.
// ---------------------------------------------------------------------------
#define BKK 64
#define NCHUNK (D_ / BKK)        // 16
#define TILE_B (128 * 128)       // 16384 bytes per tile
#define STAGE_B (2 * TILE_B)     // 32768 (A + B)
#define GEMM_SMEM (3 * STAGE_B)  // 98304

#define CP_ASYNC16(s, g) \
    asm volatile("cp.async.cg.shared.global [%0], [%1], 16;" :: "r"(s), "l"(g))
#define CP_COMMIT() asm volatile("cp.async.commit_group;" ::: "memory")
#define CP_WAIT(n)  asm volatile("cp.async.wait_group %0;" :: "n"(n) : "memory")

#define LDSM_X4(r0, r1, r2, r3, a) \
    asm volatile("ldmatrix.sync.aligned.m8n8.x4.shared.b16 {%0,%1,%2,%3}, [%4];" \
        : "=r"(r0), "=r"(r1), "=r"(r2), "=r"(r3) : "r"(a))

#define MMA16816(c, a, b) \
    asm volatile("mma.sync.aligned.m16n8k16.row.col.f32.f16.f16.f32 " \
        "{%0,%1,%2,%3}, {%4,%5,%6,%7}, {%8,%9}, {%0,%1,%2,%3};" \
        : "+f"((c)[0]), "+f"((c)[1]), "+f"((c)[2]), "+f"((c)[3]) \
        : "r"((a)[0]), "r"((a)[1]), "r"((a)[2]), "r"((a)[3]), "r"((b)[0]), "r"((b)[1]))

__device__ __forceinline__ void load_tile(uint32_t sbase, const __half* g,
                                          int row0, int kk) {
    const int tid = threadIdx.x;
#pragma unroll
    for (int j = 0; j < 4; j++) {
        int i = tid + 256 * j;         // 0..1023
        int row = i >> 3;
        int c = i & 7;
        uint32_t s = sbase + row * 128 + ((c ^ (row & 7)) << 4);
        const void* gp = g + (size_t)(row0 + row) * D_ + kk + c * 8;
        CP_ASYNC16(s, gp);
    }
}

__global__ __launch_bounds__(256, 2) void gemm_kernel(
    const __half* __restrict__ A, const __half* __restrict__ Bm,
    float* __restrict__ C, int ldc, int nmax, const float* __restrict__ bias,
    float* __restrict__ U0, __half* __restrict__ U12)
{
    extern __shared__ char smem[];
    const uint32_t sbase = smem_to_u32(smem);
    const int tid = threadIdx.x;
    const int lane = tid & 31;
    const int wid = tid >> 5;
    const int wm = wid & 3;          // 4 warps along M -> 32 rows each
    const int wn = wid >> 2;         // 2 warps along N -> 64 cols each
    const int m0 = blockIdx.y * 128;
    const int n0 = blockIdx.x * 128;

    float acc[2][8][4];
#pragma unroll
    for (int i = 0; i < 2; i++)
#pragma unroll
        for (int j = 0; j < 8; j++)
#pragma unroll
            for (int q = 0; q < 4; q++) acc[i][j][q] = 0.0f;

    // prologue: stages 0 and 1
#pragma unroll
    for (int p = 0; p < 2; p++) {
        uint32_t st = sbase + p * STAGE_B;
        load_tile(st + 0 * TILE_B, A, m0, p * BKK);
        load_tile(st + 1 * TILE_B, Bm, n0, p * BKK);
        CP_COMMIT();
    }

    const int a_roff = (lane & 7) + ((lane >> 3) & 1) * 8;
    const int a_half = (lane >> 4) & 1;
    const int b_roff = (lane & 7) + ((lane >> 4) & 1) * 8;
    const int b_half = (lane >> 3) & 1;

    int stage = 0;
    for (int k = 0; k < NCHUNK; k++) {
        if (k < NCHUNK - 1) CP_WAIT(1); else CP_WAIT(0);
        __syncthreads();

        const uint32_t st = sbase + stage * STAGE_B;
        const uint32_t aA = st, aB = st + TILE_B;

#pragma unroll
        for (int ks = 0; ks < 4; ks++) {
            uint32_t af[2][4], bf[8][2];
#pragma unroll
            for (int mi = 0; mi < 2; mi++) {
                int row = wm * 32 + mi * 16 + a_roff;
                int c = (ks * 2 + a_half) ^ (row & 7);
                LDSM_X4(af[mi][0], af[mi][1], af[mi][2], af[mi][3],
                        aA + row * 128 + (c << 4));
            }
#pragma unroll
            for (int g = 0; g < 4; g++) {
                int row = wn * 64 + g * 16 + b_roff;
                int c = (ks * 2 + b_half) ^ (row & 7);
                uint32_t r0, r1, r2, r3;
                LDSM_X4(r0, r1, r2, r3, aB + row * 128 + (c << 4));
                bf[g * 2][0] = r0; bf[g * 2][1] = r1;
                bf[g * 2 + 1][0] = r2; bf[g * 2 + 1][1] = r3;
            }
#pragma unroll
            for (int mi = 0; mi < 2; mi++)
#pragma unroll
                for (int ni = 0; ni < 8; ni++)
                    MMA16816(acc[mi][ni], af[mi], bf[ni]);
        }

        // stage (k+2)%3 is not in use by anyone: issue next loads, no extra sync
        if (k + 2 < NCHUNK) {
            int s2 = stage + 2; if (s2 >= 3) s2 -= 3;
            uint32_t stw = sbase + s2 * STAGE_B;
            const int kk = (k + 2) * BKK;
            load_tile(stw + 0 * TILE_B, A, m0, kk);
            load_tile(stw + 1 * TILE_B, Bm, n0, kk);
        }
        CP_COMMIT();
        if (++stage == 3) stage = 0;
    }

    // ----- epilogue -----
    if (U0) {
        // SRU mode: n<1024 -> u0 fp32; else u1/u2 -> fp16 U12 at col n-1024
#pragma unroll
        for (int ni = 0; ni < 8; ni++) {
            int col = n0 + wn * 64 + ni * 8 + (lane & 3) * 2;
#pragma unroll
            for (int mi = 0; mi < 2; mi++) {
                int row = m0 + wm * 32 + mi * 16 + (lane >> 2);
                if (col < D_) {
                    float* p0 = U0 + (size_t)row * D_ + col;
                    float* p1 = U0 + (size_t)(row + 8) * D_ + col;
                    *(float2*)p0 = make_float2(acc[mi][ni][0], acc[mi][ni][1]);
                    *(float2*)p1 = make_float2(acc[mi][ni][2], acc[mi][ni][3]);
                } else {
                    __half2* p0 = (__half2*)(U12 + (size_t)row * (2 * D_) + col - D_);
                    __half2* p1 = (__half2*)(U12 + (size_t)(row + 8) * (2 * D_) + col - D_);
                    *p0 = __floats2half2_rn(acc[mi][ni][0], acc[mi][ni][1]);
                    *p1 = __floats2half2_rn(acc[mi][ni][2], acc[mi][ni][3]);
                }
            }
        }
    } else {
        const bool vec = ((ldc & 1) == 0);
#pragma unroll
        for (int ni = 0; ni < 8; ni++) {
            int col = n0 + wn * 64 + ni * 8 + (lane & 3) * 2;
            float bv0 = 0.f, bv1 = 0.f;
            if (bias) {
                if (col < nmax)     bv0 = bias[col];
                if (col + 1 < nmax) bv1 = bias[col + 1];
            }
#pragma unroll
            for (int mi = 0; mi < 2; mi++) {
                int row = m0 + wm * 32 + mi * 16 + (lane >> 2);
                float* p0 = C + (size_t)row * ldc + col;
                float* p1 = C + (size_t)(row + 8) * ldc + col;
                if (vec && col + 1 < nmax) {
                    *(float2*)p0 = make_float2(acc[mi][ni][0] + bv0, acc[mi][ni][1] + bv1);
                    *(float2*)p1 = make_float2(acc[mi][ni][2] + bv0, acc[mi][ni][3] + bv1);
                } else {
                    if (col < nmax) {
                        p0[0] = acc[mi][ni][0] + bv0;
                        p1[0] = acc[mi][ni][2] + bv0;
                    }
                    if (col + 1 < nmax) {
                        p0[1] = acc[mi][ni][1] + bv1;
                        p1[1] = acc[mi][ni][3] + bv1;
                    }
                }
            }
        }
    }
}

// ---------------------------------------------------------------------------
// SRU recurrence: 2 channels per thread (d, d+1), prefetched.
// Reads u0 fp32, u1/u2 fp16, xt fp16 (in-place A update); emits fp16 h.
// ---------------------------------------------------------------------------
__global__ __launch_bounds__(128) void sru_kernel(
    const float* __restrict__ U0, const __half* __restrict__ U12,
    __half* __restrict__ A, __half* __restrict__ Aord,
    const float* __restrict__ v, const float* __restrict__ bp,
    float* __restrict__ cfin, int last)
{
    int idx = blockIdx.x * blockDim.x + threadIdx.x;   // 0 .. B_*D_/2-1
    int b = idx / (D_ / 2);
    int d = (idx % (D_ / 2)) * 2;

    const float vf0 = v[d],      vf1 = v[d + 1];
    const float vr0 = v[D_ + d], vr1 = v[D_ + d + 1];
    const float bf0 = bp[d],      bf1 = bp[d + 1];
    const float br0 = bp[D_ + d], br1 = bp[D_ + d + 1];
    float c0 = 0.0f, c1 = 0.0f;

    const size_t u0off = (size_t)b * D_ + d;
    const size_t u12off = (size_t)b * (2 * D_) + d;
    const size_t u0step = (size_t)B_ * D_;
    const size_t u12step = (size_t)B_ * (2 * D_);

    float2 u0v = *(const float2*)(U0 + u0off);
    __half2 u1v = *(const __half2*)(U12 + u12off);
    __half2 u2v = *(const __half2*)(U12 + u12off + D_);
    __half2 xtv = *(const __half2*)(A + u0off);

    for (int t = 0; t < T_; t++) {
        float2 nu0; __half2 nu1, nu2, nxt;
        if (t + 1 < T_) {
            nu0 = __ldcs((const float2*)(U0 + u0off + (size_t)(t + 1) * u0step));
            nu1 = __ldcs((const __half2*)(U12 + u12off + (size_t)(t + 1) * u12step));
            nu2 = __ldcs((const __half2*)(U12 + u12off + (size_t)(t + 1) * u12step + D_));
            nxt = __ldcs((const __half2*)(A + u0off + (size_t)(t + 1) * u0step));
        } else {
            nu0 = make_float2(0.f, 0.f);
            nu1 = nu2 = nxt = __half2half2(__float2half(0.f));
        }
        float2 u12f = __half22float2(u1v);
        float2 u22f = __half22float2(u2v);
        float2 xtf  = __half22float2(xtv);

        float f0 = 1.0f / (1.0f + __expf(-(u12f.x + vf0 * c0 + bf0)));
        float f1 = 1.0f / (1.0f + __expf(-(u12f.y + vf1 * c1 + bf1)));
        c0 = f0 * c0 + (1.0f - f0) * u0v.x;
        c1 = f1 * c1 + (1.0f - f1) * u0v.y;
        float r0 = 1.0f / (1.0f + __expf(-(u22f.x + vr0 * c0 + br0)));
        float r1 = 1.0f / (1.0f + __expf(-(u22f.y + vr1 * c1 + br1)));
        float h0 = r0 * c0 + (1.0f - r0) * xtf.x;
        float h1 = r1 * c1 + (1.0f - r1) * xtf.y;

        __half2 hv = __floats2half2_rn(h0, h1);
        if (last)
            *(__half2*)(Aord + ((size_t)b * T_ + t) * D_ + d) = hv;
        else
            *(__half2*)(A + u0off + (size_t)t * u0step) = hv;

        u0v = nu0; u1v = nu1; u2v = nu2; xtv = nxt;
    }
    *(float2*)(cfin + u0off) = make_float2(c0, c1);
}

// ---------------------------------------------------------------------------
// Launcher
// ---------------------------------------------------------------------------
extern "C" void kernel_launch(void* const* d_in, const int* in_sizes, int n_in,
                              void* d_out, int out_size)
{
    const float* x     = (const float*)d_in[0];
    const float* W1    = (const float*)d_in[2];
    const float* b1    = (const float*)d_in[3];
    const float* sru_W = (const float*)d_in[4];
    const float* sru_v = (const float*)d_in[5];
    const float* sru_b = (const float*)d_in[6];
    const float* W3    = (const float*)d_in[7];
    const float* b3    = (const float*)d_in[8];
    float* out = (float*)d_out;

    float *U0P;
    __half *U12P, *AP, *AordP, *WtP, *W3tP;
    cudaGetSymbolAddress((void**)&U0P, g_U0);
    cudaGetSymbolAddress((void**)&U12P, g_U12);
    cudaGetSymbolAddress((void**)&AP, g_A);
    cudaGetSymbolAddress((void**)&AordP, g_Aord);
    cudaGetSymbolAddress((void**)&WtP, g_Wt);
    cudaGetSymbolAddress((void**)&W3tP, g_W3t);

    cudaFuncSetAttribute(gemm_kernel, cudaFuncAttributeMaxDynamicSharedMemorySize, GEMM_SMEM);

    // Weight prep
    {
        dim3 g(N3_ / 32, D_ / 32, L_);
        wprep_sru_kernel<<<g, 256>>>(sru_W);
        dim3 g3(OPAD / 32, D_ / 32, 1);
        wprep_w3_kernel<<<g3, 256>>>(W3);
    }

    // Input projection
    proj_kernel<<<M_ / PROJ_ROWS, 256>>>(x, W1, b1);

    // SRU layers
    for (int l = 0; l < L_; l++) {
        const __half* Bh = WtP + (size_t)l * N3_ * D_;
        dim3 grid(N3_ / 128, M_ / 128);
        gemm_kernel<<<grid, 256, GEMM_SMEM>>>(AP, Bh, nullptr, 0, 0, nullptr, U0P, U12P);

        const float* vl = sru_v + (size_t)l * 2 * D_;
        const float* bl = sru_b + (size_t)l * 2 * D_;
        float* cfin = out + Y_SIZE + (size_t)l * B_ * D_;
        int last = (l == L_ - 1) ? 1 : 0;
        sru_kernel<<<(B_ * D_ / 2) / 128, 128>>>(U0P, U12P, AP, AordP, vl, bl, cfin, last);
    }

    // Output GEMM: y = h @ W3 + b3
    {
        dim3 grid(OPAD / 128, M_ / 128);
        gemm_kernel<<<grid, 256, GEMM_SMEM>>>(AordP, W3tP, out, O_, O_, b3, nullptr, nullptr);
    }
}

// round 8
// speedup vs baseline: 6.8425x; 1.1302x over previous
#include <cuda_runtime.h>
#include <cuda_fp16.h>
#include <cstdint>
#include <math.h>

// Problem dims
#define B_  64
#define T_  512
#define F_  20
#define D_  1024
#define O_  1095
#define L_  3
#define M_  (B_ * T_)        // 32768
#define N3_ (3 * D_)         // 3072
#define OPAD 1152
#define Y_SIZE ((size_t)M_ * O_)

// ---------------------------------------------------------------------------
// Scratch (static device globals)
// ---------------------------------------------------------------------------
__device__ float  g_U0[(size_t)M_ * D_];          // u0 gate pre-activation (fp32)
__device__ __half g_U12[(size_t)M_ * 2 * D_];     // u1|u2 (fp16), [row][2048]
__device__ __half g_A[(size_t)M_ * D_];           // fp16 hidden (time-major)
__device__ __half g_Aord[(size_t)M_ * D_];        // fp16 hidden (batch-major, last layer)
__device__ __half g_Wt[(size_t)L_ * N3_ * D_];    // sru_W^T fp16  [l][n][k]
__device__ __half g_W3t[(size_t)OPAD * D_];       // W3^T fp16 (zero padded)

__device__ __forceinline__ uint32_t smem_to_u32(const void* p) {
    uint32_t a;
    asm("{ .reg .u64 t; cvta.to.shared.u64 t, %1; cvt.u32.u64 %0, t; }" : "=r"(a) : "l"(p));
    return a;
}

// ---------------------------------------------------------------------------
// Input projection -> g_A (fp16), time-major
// ---------------------------------------------------------------------------
#define PROJ_ROWS 16
__global__ __launch_bounds__(256) void proj_kernel(
    const float* __restrict__ x, const float* __restrict__ W1,
    const float* __restrict__ b1)
{
    int r0 = blockIdx.x * PROJ_ROWS;
    __shared__ float xs[PROJ_ROWS][F_];
    for (int i = threadIdx.x; i < PROJ_ROWS * F_; i += blockDim.x) {
        int rr = i / F_, f = i % F_;
        int r = r0 + rr;
        int b = r % B_, t = r / B_;
        xs[rr][f] = x[((size_t)b * T_ + t) * F_ + f];
    }
    __syncthreads();
    for (int d = threadIdx.x; d < D_; d += blockDim.x) {
        float w[F_];
#pragma unroll
        for (int f = 0; f < F_; f++) w[f] = W1[f * D_ + d];
        float bb = b1[d];
#pragma unroll
        for (int rr = 0; rr < PROJ_ROWS; rr++) {
            float acc = bb;
#pragma unroll
            for (int f = 0; f < F_; f++) acc += xs[rr][f] * w[f];
            g_A[(size_t)(r0 + rr) * D_ + d] = __float2half(acc);
        }
    }
}

// ---------------------------------------------------------------------------
// Weight prep: transpose + fp16 round. sru_W (L, K=D, N=3D) -> [l][n][k]
// ---------------------------------------------------------------------------
__global__ __launch_bounds__(256) void wprep_sru_kernel(const float* __restrict__ W)
{
    __shared__ float tile[32][33];
    int l = blockIdx.z;
    int n0 = blockIdx.x * 32, k0 = blockIdx.y * 32;
    const float* Wl = W + (size_t)l * D_ * N3_;
    int tx = threadIdx.x & 31, ty = threadIdx.x >> 5;
    for (int dy = ty; dy < 32; dy += 8)
        tile[dy][tx] = Wl[(size_t)(k0 + dy) * N3_ + n0 + tx];
    __syncthreads();
    __half* oh = g_Wt + (size_t)l * N3_ * D_;
    for (int dy = ty; dy < 32; dy += 8)
        oh[(size_t)(n0 + dy) * D_ + k0 + tx] = __float2half(tile[tx][dy]);
}

__global__ __launch_bounds__(256) void wprep_w3_kernel(const float* __restrict__ W3)
{
    __shared__ float tile[32][33];
    int n0 = blockIdx.x * 32, k0 = blockIdx.y * 32;
    int tx = threadIdx.x & 31, ty = threadIdx.x >> 5;
    for (int dy = ty; dy < 32; dy += 8) {
        int n = n0 + tx;
        tile[dy][tx] = (n < O_) ? W3[(size_t)(k0 + dy) * O_ + n] : 0.0f;
    }
    __syncthreads();
    for (int dy = ty; dy < 32; dy += 8)
        g_W3t[(size_t)(n0 + dy) * D_ + k0 + tx] = __float2half(tile[tx][dy]);
}

// ---------------------------------------------------------------------------
// mma.sync fp16 GEMM (single term). C[128 x 128] per CTA.
// A: [M,K] fp16 (K-major). B: [N,K] fp16. BK=64, 3-stage cp.async pipeline.
// SMEM tiles: 128 rows x 128 bytes, 16B-chunk XOR swizzle (c ^= row&7).
// SRU mode (U0 != null): u0 cols -> fp32 U0, u1/u2 cols -> fp16 U12.
// ---------------------------------------------------------------------------
#define BKK 64
#define NCHUNK (D_ / BKK)        // 16
#define TILE_B (128 * 128)       // 16384 bytes per tile
#define STAGE_B (2 * TILE_B)     // 32768 (A + B)
#define GEMM_SMEM (3 * STAGE_B)  // 98304

#define CP_ASYNC16(s, g) \
    asm volatile("cp.async.cg.shared.global [%0], [%1], 16;" :: "r"(s), "l"(g))
#define CP_ASYNC8(s, g) \
    asm volatile("cp.async.ca.shared.global [%0], [%1], 8;" :: "r"(s), "l"(g))
#define CP_ASYNC4(s, g) \
    asm volatile("cp.async.ca.shared.global [%0], [%1], 4;" :: "r"(s), "l"(g))
#define CP_COMMIT() asm volatile("cp.async.commit_group;" ::: "memory")
#define CP_WAIT(n)  asm volatile("cp.async.wait_group %0;" :: "n"(n) : "memory")

#define LDSM_X4(r0, r1, r2, r3, a) \
    asm volatile("ldmatrix.sync.aligned.m8n8.x4.shared.b16 {%0,%1,%2,%3}, [%4];" \
        : "=r"(r0), "=r"(r1), "=r"(r2), "=r"(r3) : "r"(a))

#define MMA16816(c, a, b) \
    asm volatile("mma.sync.aligned.m16n8k16.row.col.f32.f16.f16.f32 " \
        "{%0,%1,%2,%3}, {%4,%5,%6,%7}, {%8,%9}, {%0,%1,%2,%3};" \
        : "+f"((c)[0]), "+f"((c)[1]), "+f"((c)[2]), "+f"((c)[3]) \
        : "r"((a)[0]), "r"((a)[1]), "r"((a)[2]), "r"((a)[3]), "r"((b)[0]), "r"((b)[1]))

__device__ __forceinline__ void load_tile(uint32_t sbase, const __half* g,
                                          int row0, int kk) {
    const int tid = threadIdx.x;
#pragma unroll
    for (int j = 0; j < 4; j++) {
        int i = tid + 256 * j;         // 0..1023
        int row = i >> 3;
        int c = i & 7;
        uint32_t s = sbase + row * 128 + ((c ^ (row & 7)) << 4);
        const void* gp = g + (size_t)(row0 + row) * D_ + kk + c * 8;
        CP_ASYNC16(s, gp);
    }
}

__global__ __launch_bounds__(256, 2) void gemm_kernel(
    const __half* __restrict__ A, const __half* __restrict__ Bm,
    float* __restrict__ C, int ldc, int nmax, const float* __restrict__ bias,
    float* __restrict__ U0, __half* __restrict__ U12)
{
    extern __shared__ char smem[];
    const uint32_t sbase = smem_to_u32(smem);
    const int tid = threadIdx.x;
    const int lane = tid & 31;
    const int wid = tid >> 5;
    const int wm = wid & 3;          // 4 warps along M -> 32 rows each
    const int wn = wid >> 2;         // 2 warps along N -> 64 cols each
    const int m0 = blockIdx.y * 128;
    const int n0 = blockIdx.x * 128;

    float acc[2][8][4];
#pragma unroll
    for (int i = 0; i < 2; i++)
#pragma unroll
        for (int j = 0; j < 8; j++)
#pragma unroll
            for (int q = 0; q < 4; q++) acc[i][j][q] = 0.0f;

    // prologue: stages 0 and 1
#pragma unroll
    for (int p = 0; p < 2; p++) {
        uint32_t st = sbase + p * STAGE_B;
        load_tile(st + 0 * TILE_B, A, m0, p * BKK);
        load_tile(st + 1 * TILE_B, Bm, n0, p * BKK);
        CP_COMMIT();
    }

    const int a_roff = (lane & 7) + ((lane >> 3) & 1) * 8;
    const int a_half = (lane >> 4) & 1;
    const int b_roff = (lane & 7) + ((lane >> 4) & 1) * 8;
    const int b_half = (lane >> 3) & 1;

    int stage = 0;
    for (int k = 0; k < NCHUNK; k++) {
        if (k < NCHUNK - 1) CP_WAIT(1); else CP_WAIT(0);
        __syncthreads();

        const uint32_t st = sbase + stage * STAGE_B;
        const uint32_t aA = st, aB = st + TILE_B;

#pragma unroll
        for (int ks = 0; ks < 4; ks++) {
            uint32_t af[2][4], bf[8][2];
#pragma unroll
            for (int mi = 0; mi < 2; mi++) {
                int row = wm * 32 + mi * 16 + a_roff;
                int c = (ks * 2 + a_half) ^ (row & 7);
                LDSM_X4(af[mi][0], af[mi][1], af[mi][2], af[mi][3],
                        aA + row * 128 + (c << 4));
            }
#pragma unroll
            for (int g = 0; g < 4; g++) {
                int row = wn * 64 + g * 16 + b_roff;
                int c = (ks * 2 + b_half) ^ (row & 7);
                uint32_t r0, r1, r2, r3;
                LDSM_X4(r0, r1, r2, r3, aB + row * 128 + (c << 4));
                bf[g * 2][0] = r0; bf[g * 2][1] = r1;
                bf[g * 2 + 1][0] = r2; bf[g * 2 + 1][1] = r3;
            }
#pragma unroll
            for (int mi = 0; mi < 2; mi++)
#pragma unroll
                for (int ni = 0; ni < 8; ni++)
                    MMA16816(acc[mi][ni], af[mi], bf[ni]);
        }

        // stage (k+2)%3 is not in use by anyone: issue next loads, no extra sync
        if (k + 2 < NCHUNK) {
            int s2 = stage + 2; if (s2 >= 3) s2 -= 3;
            uint32_t stw = sbase + s2 * STAGE_B;
            const int kk = (k + 2) * BKK;
            load_tile(stw + 0 * TILE_B, A, m0, kk);
            load_tile(stw + 1 * TILE_B, Bm, n0, kk);
        }
        CP_COMMIT();
        if (++stage == 3) stage = 0;
    }

    // ----- epilogue -----
    if (U0) {
        // SRU mode: n<1024 -> u0 fp32; else u1/u2 -> fp16 U12 at col n-1024
#pragma unroll
        for (int ni = 0; ni < 8; ni++) {
            int col = n0 + wn * 64 + ni * 8 + (lane & 3) * 2;
#pragma unroll
            for (int mi = 0; mi < 2; mi++) {
                int row = m0 + wm * 32 + mi * 16 + (lane >> 2);
                if (col < D_) {
                    float* p0 = U0 + (size_t)row * D_ + col;
                    float* p1 = U0 + (size_t)(row + 8) * D_ + col;
                    *(float2*)p0 = make_float2(acc[mi][ni][0], acc[mi][ni][1]);
                    *(float2*)p1 = make_float2(acc[mi][ni][2], acc[mi][ni][3]);
                } else {
                    __half2* p0 = (__half2*)(U12 + (size_t)row * (2 * D_) + col - D_);
                    __half2* p1 = (__half2*)(U12 + (size_t)(row + 8) * (2 * D_) + col - D_);
                    *p0 = __floats2half2_rn(acc[mi][ni][0], acc[mi][ni][1]);
                    *p1 = __floats2half2_rn(acc[mi][ni][2], acc[mi][ni][3]);
                }
            }
        }
    } else {
        const bool vec = ((ldc & 1) == 0);
#pragma unroll
        for (int ni = 0; ni < 8; ni++) {
            int col = n0 + wn * 64 + ni * 8 + (lane & 3) * 2;
            float bv0 = 0.f, bv1 = 0.f;
            if (bias) {
                if (col < nmax)     bv0 = bias[col];
                if (col + 1 < nmax) bv1 = bias[col + 1];
            }
#pragma unroll
            for (int mi = 0; mi < 2; mi++) {
                int row = m0 + wm * 32 + mi * 16 + (lane >> 2);
                float* p0 = C + (size_t)row * ldc + col;
                float* p1 = C + (size_t)(row + 8) * ldc + col;
                if (vec && col + 1 < nmax) {
                    *(float2*)p0 = make_float2(acc[mi][ni][0] + bv0, acc[mi][ni][1] + bv1);
                    *(float2*)p1 = make_float2(acc[mi][ni][2] + bv0, acc[mi][ni][3] + bv1);
                } else {
                    if (col < nmax) {
                        p0[0] = acc[mi][ni][0] + bv0;
                        p1[0] = acc[mi][ni][2] + bv0;
                    }
                    if (col + 1 < nmax) {
                        p0[1] = acc[mi][ni][1] + bv1;
                        p1[1] = acc[mi][ni][3] + bv1;
                    }
                }
            }
        }
    }
}

// ---------------------------------------------------------------------------
// SRU recurrence: 2 channels per thread, cp.async SMEM ring of depth 8.
// Each thread stages ONLY its own channel data; wait_group makes a thread's
// own cp.async writes visible to itself, so no __syncthreads needed.
// ---------------------------------------------------------------------------
#define SPFD 8   // ring depth; T_ % SPFD == 0
__global__ __launch_bounds__(128) void sru_kernel(
    const float* __restrict__ U0, const __half* __restrict__ U12,
    __half* __restrict__ A, __half* __restrict__ Aord,
    const float* __restrict__ v, const float* __restrict__ bp,
    float* __restrict__ cfin, int last)
{
    __shared__ float2  s_u0[SPFD][128];
    __shared__ __half2 s_u1[SPFD][128];
    __shared__ __half2 s_u2[SPFD][128];
    __shared__ __half2 s_xt[SPFD][128];

    const int tid = threadIdx.x;
    int idx = blockIdx.x * blockDim.x + tid;   // 0 .. B_*D_/2-1
    int b = idx / (D_ / 2);
    int d = (idx % (D_ / 2)) * 2;

    const float vf0 = v[d],      vf1 = v[d + 1];
    const float vr0 = v[D_ + d], vr1 = v[D_ + d + 1];
    const float bf0 = bp[d],      bf1 = bp[d + 1];
    const float br0 = bp[D_ + d], br1 = bp[D_ + d + 1];
    float c0 = 0.0f, c1 = 0.0f;

    const size_t u0off = (size_t)b * D_ + d;
    const size_t u12off = (size_t)b * (2 * D_) + d;
    const size_t u0step = (size_t)B_ * D_;
    const size_t u12step = (size_t)B_ * (2 * D_);

    const uint32_t su0 = smem_to_u32(&s_u0[0][tid]);
    const uint32_t su1 = smem_to_u32(&s_u1[0][tid]);
    const uint32_t su2 = smem_to_u32(&s_u2[0][tid]);
    const uint32_t sxt = smem_to_u32(&s_xt[0][tid]);

    // prologue: stage timesteps 0..SPFD-1, one commit group each
#pragma unroll
    for (int p = 0; p < SPFD; p++) {
        CP_ASYNC8(su0 + p * 128 * 8, U0 + u0off + (size_t)p * u0step);
        CP_ASYNC4(su1 + p * 128 * 4, U12 + u12off + (size_t)p * u12step);
        CP_ASYNC4(su2 + p * 128 * 4, U12 + u12off + (size_t)p * u12step + D_);
        CP_ASYNC4(sxt + p * 128 * 4, A + u0off + (size_t)p * u0step);
        CP_COMMIT();
    }

    for (int t = 0; t < T_; t++) {
        const int slot = t & (SPFD - 1);
        CP_WAIT(7);   // oldest group (stage t) complete; visible to this thread

        float2 u0v  = s_u0[slot][tid];
        float2 u12f = __half22float2(s_u1[slot][tid]);
        float2 u22f = __half22float2(s_u2[slot][tid]);
        float2 xtf  = __half22float2(s_xt[slot][tid]);

        // refill slot with stage t+SPFD (values above already in registers)
        if (t + SPFD < T_) {
            CP_ASYNC8(su0 + slot * 128 * 8, U0 + u0off + (size_t)(t + SPFD) * u0step);
            CP_ASYNC4(su1 + slot * 128 * 4, U12 + u12off + (size_t)(t + SPFD) * u12step);
            CP_ASYNC4(su2 + slot * 128 * 4, U12 + u12off + (size_t)(t + SPFD) * u12step + D_);
            CP_ASYNC4(sxt + slot * 128 * 4, A + u0off + (size_t)(t + SPFD) * u0step);
        }
        CP_COMMIT();  // commit every iteration to keep group counts aligned

        float f0 = 1.0f / (1.0f + __expf(-(u12f.x + vf0 * c0 + bf0)));
        float f1 = 1.0f / (1.0f + __expf(-(u12f.y + vf1 * c1 + bf1)));
        c0 = f0 * c0 + (1.0f - f0) * u0v.x;
        c1 = f1 * c1 + (1.0f - f1) * u0v.y;
        float r0 = 1.0f / (1.0f + __expf(-(u22f.x + vr0 * c0 + br0)));
        float r1 = 1.0f / (1.0f + __expf(-(u22f.y + vr1 * c1 + br1)));
        float h0 = r0 * c0 + (1.0f - r0) * xtf.x;
        float h1 = r1 * c1 + (1.0f - r1) * xtf.y;

        __half2 hv = __floats2half2_rn(h0, h1);
        if (last)
            *(__half2*)(Aord + ((size_t)b * T_ + t) * D_ + d) = hv;
        else
            *(__half2*)(A + u0off + (size_t)t * u0step) = hv;
    }
    *(float2*)(cfin + u0off) = make_float2(c0, c1);
}

// ---------------------------------------------------------------------------
// Launcher
// ---------------------------------------------------------------------------
extern "C" void kernel_launch(void* const* d_in, const int* in_sizes, int n_in,
                              void* d_out, int out_size)
{
    const float* x     = (const float*)d_in[0];
    const float* W1    = (const float*)d_in[2];
    const float* b1    = (const float*)d_in[3];
    const float* sru_W = (const float*)d_in[4];
    const float* sru_v = (const float*)d_in[5];
    const float* sru_b = (const float*)d_in[6];
    const float* W3    = (const float*)d_in[7];
    const float* b3    = (const float*)d_in[8];
    float* out = (float*)d_out;

    float *U0P;
    __half *U12P, *AP, *AordP, *WtP, *W3tP;
    cudaGetSymbolAddress((void**)&U0P, g_U0);
    cudaGetSymbolAddress((void**)&U12P, g_U12);
    cudaGetSymbolAddress((void**)&AP, g_A);
    cudaGetSymbolAddress((void**)&AordP, g_Aord);
    cudaGetSymbolAddress((void**)&WtP, g_Wt);
    cudaGetSymbolAddress((void**)&W3tP, g_W3t);

    cudaFuncSetAttribute(gemm_kernel, cudaFuncAttributeMaxDynamicSharedMemorySize, GEMM_SMEM);

    // Weight prep
    {
        dim3 g(N3_ / 32, D_ / 32, L_);
        wprep_sru_kernel<<<g, 256>>>(sru_W);
        dim3 g3(OPAD / 32, D_ / 32, 1);
        wprep_w3_kernel<<<g3, 256>>>(W3);
    }

    // Input projection
    proj_kernel<<<M_ / PROJ_ROWS, 256>>>(x, W1, b1);

    // SRU layers
    for (int l = 0; l < L_; l++) {
        const __half* Bh = WtP + (size_t)l * N3_ * D_;
        dim3 grid(N3_ / 128, M_ / 128);
        gemm_kernel<<<grid, 256, GEMM_SMEM>>>(AP, Bh, nullptr, 0, 0, nullptr, U0P, U12P);

        const float* vl = sru_v + (size_t)l * 2 * D_;
        const float* bl = sru_b + (size_t)l * 2 * D_;
        float* cfin = out + Y_SIZE + (size_t)l * B_ * D_;
        int last = (l == L_ - 1) ? 1 : 0;
        sru_kernel<<<(B_ * D_ / 2) / 128, 128>>>(U0P, U12P, AP, AordP, vl, bl, cfin, last);
    }

    // Output GEMM: y = h @ W3 + b3
    {
        dim3 grid(OPAD / 128, M_ / 128);
        gemm_kernel<<<grid, 256, GEMM_SMEM>>>(AordP, W3tP, out, O_, O_, b3, nullptr, nullptr);
    }
}